// round 1
// baseline (speedup 1.0000x reference)
#include <cuda_runtime.h>
#include <math.h>

#define NUM_BINS 16
#define BOUND 3.0f
#define MIN_BIN_WIDTH 0.001f
#define MIN_BIN_HEIGHT 0.001f
#define MIN_DERIVATIVE 0.001f
#define MIN_LAMBDA 0.025f
#define EPS_C 1e-6f

#define TPB 128          // elements (threads) per block
#define P 63             // params per element (4*K-1)

__device__ __forceinline__ float softplus_f(float v) {
    // log1p(exp(-|v|)) + max(v,0)  (stable, matches jax.nn.softplus)
    return fmaxf(v, 0.0f) + log1pf(expf(-fabsf(v)));
}

__global__ __launch_bounds__(TPB) void lrs_kernel(
    const float* __restrict__ inputs,
    const float* __restrict__ params,
    float* __restrict__ out,
    int n)
{
    __shared__ float sm[TPB * P];   // 128*63*4 = 32256 B

    const int tid  = threadIdx.x;
    const int base_elem = blockIdx.x * TPB;

    // ---- cooperative coalesced staging: 128*63 floats = 2016 float4 ----
    {
        const float4* gsrc = reinterpret_cast<const float4*>(params + (size_t)base_elem * P);
        float4* sdst = reinterpret_cast<float4*>(sm);
        const int nvec = (TPB * P) / 4;   // 2016
        int remaining_elems = n - base_elem;
        if (remaining_elems >= TPB) {
            #pragma unroll
            for (int i = 0; i < nvec / TPB; i++) {
                sdst[i * TPB + tid] = gsrc[i * TPB + tid];
            }
            // nvec = 2016 = 15.75*128 -> handle tail vectors
            int tail_start = (nvec / TPB) * TPB;   // 1920
            int idx = tail_start + tid;
            if (idx < nvec) sdst[idx] = gsrc[idx];
        } else {
            // ragged last block: scalar loads with bounds check
            int total = remaining_elems * P;
            for (int i = tid; i < total; i += TPB) {
                sm[i] = params[(size_t)base_elem * P + i];
            }
        }
    }
    __syncthreads();

    const int elem = base_elem + tid;
    if (elem >= n) return;

    float* p = sm + tid * P;      // this thread's 63 params (bank-conflict-free stride)
    const float x = inputs[elem];

    // ================= widths: softmax -> knots -> bin search =================
    // max
    float m = p[0];
    #pragma unroll
    for (int k = 1; k < NUM_BINS; k++) m = fmaxf(m, p[k]);
    // exp + sum (store exp back)
    float s = 0.0f;
    #pragma unroll
    for (int k = 0; k < NUM_BINS; k++) {
        float e = expf(p[k] - m);
        p[k] = e;
        s += e;
    }
    const float wscale = (1.0f - MIN_BIN_WIDTH * NUM_BINS) / s;

    // cumsum -> knots (store knots[1..15] in p[0..14]); track bin
    int b = (-BOUND + EPS_C <= x) ? 0 : -1;
    {
        float cum = 0.0f;
        #pragma unroll
        for (int k = 0; k < NUM_BINS; k++) {
            float wk = MIN_BIN_WIDTH + wscale * p[k];
            cum += wk;
            float knot = (k == NUM_BINS - 1) ? BOUND : fmaf(cum, 2.0f * BOUND, -BOUND);
            if (k < NUM_BINS - 1) p[k] = knot;
            if (knot + EPS_C <= x) b = k + 1;
        }
    }
    const int bin = min(max(b, 0), NUM_BINS - 1);

    const float cwL = (bin == 0) ? -BOUND : p[bin - 1];
    const float cwR = (bin == NUM_BINS - 1) ? BOUND : p[bin];
    const float in_w = cwR - cwL;   // widths = diff(knots), matches reference

    // ================= heights: softmax -> knots, select bin =================
    float* ph = p + NUM_BINS;
    float mh = ph[0];
    #pragma unroll
    for (int k = 1; k < NUM_BINS; k++) mh = fmaxf(mh, ph[k]);
    float sh = 0.0f;
    #pragma unroll
    for (int k = 0; k < NUM_BINS; k++) {
        float e = expf(ph[k] - mh);
        ph[k] = e;
        sh += e;
    }
    const float hscale = (1.0f - MIN_BIN_HEIGHT * NUM_BINS) / sh;
    {
        float cum = 0.0f;
        #pragma unroll
        for (int k = 0; k < NUM_BINS; k++) {
            float hk = MIN_BIN_HEIGHT + hscale * ph[k];
            cum += hk;
            float knot = (k == NUM_BINS - 1) ? BOUND : fmaf(cum, 2.0f * BOUND, -BOUND);
            if (k < NUM_BINS - 1) ph[k] = knot;
        }
    }
    const float chL = (bin == 0) ? -BOUND : ph[bin - 1];
    const float chR = (bin == NUM_BINS - 1) ? BOUND : ph[bin];
    const float in_h = chR - chL;

    // ================= derivatives (only 2 softplus needed) =================
    // d raw params: p[32..46] (15 values); derivatives = [edge, mind+sp(d0..14), edge]
    const float* pd = sm + tid * P + 2 * NUM_BINS;           // offset 32
    const float edge = 1.0f - MIN_DERIVATIVE;
    const float dL = (bin == 0) ? edge : (MIN_DERIVATIVE + softplus_f(pd[bin - 1]));
    const float dR = (bin == NUM_BINS - 1) ? edge : (MIN_DERIVATIVE + softplus_f(pd[bin]));

    // ================= lambda (1 sigmoid) =================
    const float* pl = sm + tid * P + (3 * NUM_BINS - 1);      // offset 47
    const float lam_raw = pl[bin];
    const float sig = 1.0f / (1.0f + expf(-lam_raw));
    const float lam = fmaf(1.0f - 2.0f * MIN_LAMBDA, sig, MIN_LAMBDA);

    // ================= spline evaluation =================
    const float delta = in_h / in_w;
    const float wb = sqrtf(dL / dR);
    const float lwa = lam;
    const float lwb = lam * wb;
    const float wc = (lwa * dL + (wb - lwb) * dR) / delta;
    const float ya = chL;
    const float yb = in_h + chL;
    const float l1 = 1.0f - lam;
    const float yc = (lwb * yb + l1 * ya) / (l1 + lwb);

    const float theta = (x - cwL) / in_w;
    const bool ind = theta <= lam;
    const float ltheta = lam - theta;
    const float wcyc = wc * yc;
    const float wcyctheta = wcyc * theta;
    const float wbyb = wb * yb;
    const float numerator   = ind ? (wcyctheta + ya * ltheta)
                                  : ((wcyc - wcyctheta) - wbyb * ltheta);
    const float wctheta = wc * theta;
    const float denominator = ind ? (wctheta + ltheta)
                                  : ((wc - wctheta) - wb * ltheta);
    const float result = numerator / denominator;

    const float dnum = wc * (ind ? (lam * (yc - ya)) : ((wb - lwb) * (yb - yc))) / in_w;
    const float lad = logf(dnum) - 2.0f * logf(fabsf(denominator));

    const bool outside = (x < -BOUND) || (x > BOUND);
    out[elem]     = outside ? x : result;
    out[n + elem] = outside ? 0.0f : lad;
}

extern "C" void kernel_launch(void* const* d_in, const int* in_sizes, int n_in,
                              void* d_out, int out_size) {
    const float* inputs = (const float*)d_in[0];
    const float* params = (const float*)d_in[1];
    float* out = (float*)d_out;
    int n = in_sizes[0];               // 16384*64 elements
    int blocks = (n + TPB - 1) / TPB;
    lrs_kernel<<<blocks, TPB>>>(inputs, params, out, n);
}